// round 14
// baseline (speedup 1.0000x reference)
#include <cuda_runtime.h>
#include <cuda_fp16.h>
#include <cstdint>

#define B_   4
#define T_   4096
#define NH   16
#define NKV  8
#define D_   128
#define WIN  1024
#define BM   128
#define BN   64
#define NTHREADS 320          // 8 consumer warps + 2 producer warps
#define NCONS    256

// fp16 tiles, rows padded to 136 elements = 272 bytes (272 mod 128 = 16 ->
// ldmatrix 8-row groups tile the 128B space exactly: conflict-free)
#define ROWB 272
#define QHI_OFF 0                       // 128 x 136 f16 = 34816 B
#define QLO_OFF 34816
#define BUF_OFF 69632                   // double-buffered K/V f16 tiles
#define KHI_O   0                       // 64 x 136 f16 = 17408 B
#define KLO_O   17408
#define V_O     34816
#define BUFSZ   52224
#define SMEM_BYTES 174080               // 170 KB -> 1 CTA/SM

// named barriers: FULL[b] = 1+b (producer done filling b),
//                 EMPTY[b] = 3+b (consumers done reading b)
#define BAR_SYNC(id)   asm volatile("bar.sync %0, %1;"   :: "r"(id), "r"(NTHREADS) : "memory")
#define BAR_ARRIVE(id) asm volatile("bar.arrive %0, %1;" :: "r"(id), "r"(NTHREADS) : "memory")

__device__ __forceinline__ void ldsm_x4(uint32_t (&r)[4], uint32_t addr) {
    asm volatile("ldmatrix.sync.aligned.m8n8.x4.shared.b16 {%0,%1,%2,%3}, [%4];"
                 : "=r"(r[0]), "=r"(r[1]), "=r"(r[2]), "=r"(r[3]) : "r"(addr));
}
__device__ __forceinline__ void ldsm_x4_t(uint32_t (&r)[4], uint32_t addr) {
    asm volatile("ldmatrix.sync.aligned.m8n8.x4.trans.shared.b16 {%0,%1,%2,%3}, [%4];"
                 : "=r"(r[0]), "=r"(r[1]), "=r"(r[2]), "=r"(r[3]) : "r"(addr));
}
#define MMA(C, A, b0, b1) asm volatile( \
    "mma.sync.aligned.m16n8k16.row.col.f32.f16.f16.f32 " \
    "{%0,%1,%2,%3}, {%4,%5,%6,%7}, {%8,%9}, {%0,%1,%2,%3};" \
    : "+f"((C)[0]), "+f"((C)[1]), "+f"((C)[2]), "+f"((C)[3]) \
    : "r"((A)[0]), "r"((A)[1]), "r"((A)[2]), "r"((A)[3]), "r"(b0), "r"(b1))

__device__ __forceinline__ uint32_t hbits(__half2 v) {
    return *reinterpret_cast<uint32_t*>(&v);
}
__device__ __forceinline__ uint32_t packh2(float x, float y) {
    __half2 h = __floats2half2_rn(x, y);
    return hbits(h);
}
// split a float pair into (hi, lo) packed f16x2
__device__ __forceinline__ void split2h(float x, float y, uint32_t &hi, uint32_t &lo) {
    __half2 h = __floats2half2_rn(x, y);
    float2 g = __half22float2(h);
    __half2 l = __floats2half2_rn(x - g.x, y - g.y);
    hi = hbits(h); lo = hbits(l);
}

__global__ void __launch_bounds__(NTHREADS, 1)
swa_mma_kernel(const float* __restrict__ Q, const float* __restrict__ K,
               const float* __restrict__ V, float* __restrict__ Out)
{
    extern __shared__ char smem[];
    uint32_t sbase;
    asm("{ .reg .u64 t; cvta.to.shared.u64 t, %1; cvt.u32.u64 %0, t; }"
        : "=r"(sbase) : "l"(smem));

    const int tid  = threadIdx.x;
    const int lane = tid & 31;
    const int wid  = tid >> 5;
    const int m0   = blockIdx.x * BM;
    const int h    = blockIdx.y;
    const int bb   = blockIdx.z;
    const int kh   = h >> 1;

    const int kb0 = (m0 >= WIN) ? ((m0 - WIN) >> 6) : 0;
    const int kbm = (m0 >> 6) + 1;

    const size_t kvhead = (size_t)(bb * T_) * (NKV * D_) + (size_t)kh * D_;

    if (wid >= 8) {
        // ================= PRODUCER (warps 8-9, 64 threads) =================
        const int p = tid - NCONS;
        for (int t = kb0; t <= kbm; t++) {
            const int b = (t - kb0) & 1;
            if (t - kb0 >= 2) BAR_SYNC(3 + b);        // wait consumers freed b
            const size_t kvb = kvhead + (size_t)(t * BN) * (NKV * D_);
            const int bo = BUF_OFF + b * BUFSZ;
            #pragma unroll 4
            for (int i = 0; i < 32; i++) {
                int idx = p + (i << 6);               // 2048 float4s / 64 thr
                int key = idx >> 5, d4 = (idx & 31) << 2;
                size_t g = kvb + (size_t)key * (NKV * D_) + d4;
                float4 fk = *(const float4*)(K + g);
                float4 fv = *(const float4*)(V + g);
                int off = bo + key * ROWB + d4 * 2;
                uint32_t h0, l0, h1, l1;
                split2h(fk.x, fk.y, h0, l0);
                split2h(fk.z, fk.w, h1, l1);
                *(uint2*)(smem + off + KHI_O) = make_uint2(h0, h1);
                *(uint2*)(smem + off + KLO_O) = make_uint2(l0, l1);
                h0 = packh2(fv.x, fv.y);
                h1 = packh2(fv.z, fv.w);
                *(uint2*)(smem + off + V_O) = make_uint2(h0, h1);
            }
            BAR_SYNC(1 + b);                          // publish FULL[b]
        }
        return;
    }

    // ================= CONSUMERS (warps 0-7, 256 threads) =================
    const int rb = wid * 16;            // warp owns rows [16w, 16w+16)
    const int tq = lane >> 2;           // 0..7
    const int tr = lane & 3;            // 0..3

    // ---- load + split Q tile (128 x 128) ----
    {
        const size_t qbase = ((size_t)(bb * T_ + m0) * NH + h) * D_;
        #pragma unroll
        for (int i = 0; i < 16; i++) {
            int idx = tid + i * NCONS;               // 4096 float4s
            int row = idx >> 5, c4 = (idx & 31) << 2;
            float4 f = *(const float4*)(Q + qbase + (size_t)row * (NH * D_) + c4);
            uint32_t h0, l0, h1, l1;
            split2h(f.x, f.y, h0, l0);
            split2h(f.z, f.w, h1, l1);
            int off = row * ROWB + c4 * 2;
            *(uint2*)(smem + QHI_OFF + off) = make_uint2(h0, h1);
            *(uint2*)(smem + QLO_OFF + off) = make_uint2(l0, l1);
        }
    }

    // ldmatrix base addresses (lane-dependent parts precomputed)
    const uint32_t a_q_hi = sbase + QHI_OFF + (rb + (lane & 15)) * ROWB + ((lane >> 4) << 3) * 2;
    const uint32_t a_q_lo = a_q_hi + (QLO_OFF - QHI_OFF);
    const int k_row = ((lane >> 4) << 3) + (lane & 7);
    const int k_col = (((lane >> 3) & 1) << 3);
    const uint32_t a_k_hi = sbase + BUF_OFF + KHI_O + k_row * ROWB + k_col * 2;
    const uint32_t a_k_lo = a_k_hi + (KLO_O - KHI_O);
    const int v_row = (((lane >> 3) & 1) << 3) + (lane & 7);
    const int v_col = ((lane >> 4) << 3);
    const uint32_t a_v = sbase + BUF_OFF + V_O + v_row * ROWB + v_col * 2;

    // O accumulators: 16 d-tiles x 4 f32  (c0,c1 row R0; c2,c3 row R1)
    float O[16][4];
    #pragma unroll
    for (int j = 0; j < 16; j++)
        #pragma unroll
        for (int e = 0; e < 4; e++) O[j][e] = 0.f;

    float mr0 = -1e29f, mr1 = -1e29f, lr0 = 0.f, lr1 = 0.f;

    for (int t = kb0; t <= kbm; t++) {
        const int n0 = t * BN;
        const int b  = (t - kb0) & 1;
        const uint32_t bofs = b * BUFSZ;
        const bool need_mask = (n0 >= m0) || (n0 + WIN < m0 + BM);

        BAR_SYNC(1 + b);   // wait FULL[b] (also drains our Q STS on 1st iter)

        // ---- S = Q K^T : 16 rows x 64 keys per warp, 3-MMA f16 split ----
        float S[8][4];
        #pragma unroll
        for (int j = 0; j < 8; j++)
            #pragma unroll
            for (int e = 0; e < 4; e++) S[j][e] = 0.f;

        #pragma unroll
        for (int ks = 0; ks < 8; ks++) {            // k = 16*ks over d=128
            uint32_t ah[4], al[4], bh[4][4], bl[4][4];
            ldsm_x4(ah, a_q_hi + ks * 32);
            ldsm_x4(al, a_q_lo + ks * 32);
            #pragma unroll
            for (int np = 0; np < 4; np++)
                ldsm_x4(bh[np], a_k_hi + bofs + np * 16 * ROWB + ks * 32);
            #pragma unroll
            for (int np = 0; np < 4; np++) {        // term 1: Qhi * Khi
                MMA(S[2*np],   ah, bh[np][0], bh[np][1]);
                MMA(S[2*np+1], ah, bh[np][2], bh[np][3]);
            }
            #pragma unroll
            for (int np = 0; np < 4; np++) {        // term 2: Qlo * Khi
                MMA(S[2*np],   al, bh[np][0], bh[np][1]);
                MMA(S[2*np+1], al, bh[np][2], bh[np][3]);
            }
            #pragma unroll
            for (int np = 0; np < 4; np++)
                ldsm_x4(bl[np], a_k_lo + bofs + np * 16 * ROWB + ks * 32);
            #pragma unroll
            for (int np = 0; np < 4; np++) {        // term 3: Qhi * Klo
                MMA(S[2*np],   ah, bl[np][0], bl[np][1]);
                MMA(S[2*np+1], ah, bl[np][2], bl[np][3]);
            }
        }

        if (need_mask) {
            const int q0 = m0 + rb + tq, q1 = q0 + 8;
            #pragma unroll
            for (int j = 0; j < 8; j++) {
                #pragma unroll
                for (int e = 0; e < 2; e++) {
                    int kp = n0 + 8 * j + 2 * tr + e;
                    if (kp > q0 || kp + WIN <= q0) S[j][e]     = -1e30f;
                    if (kp > q1 || kp + WIN <= q1) S[j][2 + e] = -1e30f;
                }
            }
        }

        // ---- online softmax (rows fully warp-private; quad reductions) ----
        float mx0 = -1e30f, mx1 = -1e30f;
        #pragma unroll
        for (int j = 0; j < 8; j++) {
            mx0 = fmaxf(mx0, fmaxf(S[j][0], S[j][1]));
            mx1 = fmaxf(mx1, fmaxf(S[j][2], S[j][3]));
        }
        mx0 = fmaxf(mx0, __shfl_xor_sync(0xffffffffu, mx0, 1));
        mx0 = fmaxf(mx0, __shfl_xor_sync(0xffffffffu, mx0, 2));
        mx1 = fmaxf(mx1, __shfl_xor_sync(0xffffffffu, mx1, 1));
        mx1 = fmaxf(mx1, __shfl_xor_sync(0xffffffffu, mx1, 2));
        const float mn0 = fmaxf(mr0, mx0), mn1 = fmaxf(mr1, mx1);
        const float sc0 = __expf(mr0 - mn0), sc1 = __expf(mr1 - mn1);
        mr0 = mn0; mr1 = mn1;

        float s0 = 0.f, s1 = 0.f;
        #pragma unroll
        for (int j = 0; j < 8; j++) {
            S[j][0] = __expf(S[j][0] - mn0); s0 += S[j][0];
            S[j][1] = __expf(S[j][1] - mn0); s0 += S[j][1];
            S[j][2] = __expf(S[j][2] - mn1); s1 += S[j][2];
            S[j][3] = __expf(S[j][3] - mn1); s1 += S[j][3];
        }
        s0 += __shfl_xor_sync(0xffffffffu, s0, 1);
        s0 += __shfl_xor_sync(0xffffffffu, s0, 2);
        s1 += __shfl_xor_sync(0xffffffffu, s1, 1);
        s1 += __shfl_xor_sync(0xffffffffu, s1, 2);
        lr0 = lr0 * sc0 + s0;
        lr1 = lr1 * sc1 + s1;

        #pragma unroll
        for (int j = 0; j < 16; j++) {
            O[j][0] *= sc0; O[j][1] *= sc0;
            O[j][2] *= sc1; O[j][3] *= sc1;
        }

        // ---- O += P V : P single-f16, V single-f16 ----
        #pragma unroll
        for (int j = 0; j < 4; j++) {               // key k-steps (16 keys)
            uint32_t ph[4];
            ph[0] = packh2(S[2*j][0],   S[2*j][1]);
            ph[1] = packh2(S[2*j][2],   S[2*j][3]);
            ph[2] = packh2(S[2*j+1][0], S[2*j+1][1]);
            ph[3] = packh2(S[2*j+1][2], S[2*j+1][3]);
            uint32_t bv[8][4];
            #pragma unroll
            for (int dp = 0; dp < 8; dp++)
                ldsm_x4_t(bv[dp], a_v + bofs + j * 16 * ROWB + dp * 32);
            #pragma unroll
            for (int dp = 0; dp < 8; dp++) {
                MMA(O[2*dp],   ph, bv[dp][0], bv[dp][1]);
                MMA(O[2*dp+1], ph, bv[dp][2], bv[dp][3]);
            }
        }

        if (t + 2 <= kbm) BAR_ARRIVE(3 + b);        // release EMPTY[b]
    }

    // ---- epilogue: normalize and store ----
    const float inv0 = 1.0f / lr0, inv1 = 1.0f / lr1;
    const int r0g = m0 + rb + tq;
    const size_t ob0 = ((size_t)(bb * T_ + r0g) * NH + h) * D_;
    const size_t ob1 = ((size_t)(bb * T_ + r0g + 8) * NH + h) * D_;
    #pragma unroll
    for (int j = 0; j < 16; j++) {
        int col = 8 * j + 2 * tr;
        *(float2*)(Out + ob0 + col) = make_float2(O[j][0] * inv0, O[j][1] * inv0);
        *(float2*)(Out + ob1 + col) = make_float2(O[j][2] * inv1, O[j][3] * inv1);
    }
}

extern "C" void kernel_launch(void* const* d_in, const int* in_sizes, int n_in,
                              void* d_out, int out_size) {
    (void)in_sizes; (void)n_in; (void)out_size;
    const float* Q = (const float*)d_in[0];
    const float* K = (const float*)d_in[1];
    const float* V = (const float*)d_in[2];
    float* O = (float*)d_out;

    cudaFuncSetAttribute(swa_mma_kernel,
                         cudaFuncAttributeMaxDynamicSharedMemorySize, SMEM_BYTES);

    dim3 grid(T_ / BM, NH, B_);   // 32 x 16 x 4 = 2048 CTAs
    swa_mma_kernel<<<grid, NTHREADS, SMEM_BYTES>>>(Q, K, V, O);
}

// round 15
// speedup vs baseline: 1.6971x; 1.6971x over previous
#include <cuda_runtime.h>
#include <cuda_fp16.h>
#include <cstdint>

#define B_   4
#define T_   4096
#define NH   16
#define NKV  8
#define D_   128
#define WIN  1024
#define BM   128
#define BN   64
#define NTHREADS 320          // 8 consumer warps + 2 producer warps
#define NCONS    256

// fp16 tiles, rows padded to 136 elements = 272 bytes (272 mod 128 = 16 ->
// ldmatrix 8-row groups tile the 128B space exactly: conflict-free)
#define ROWB 272
#define QHI_OFF 0                       // 128 x 136 f16 = 34816 B
#define QLO_OFF 34816
#define BUF_OFF 69632                   // double-buffered K/V f16 tiles
#define KHI_O   0                       // 64 x 136 f16 = 17408 B
#define KLO_O   17408
#define V_O     34816
#define BUFSZ   52224
#define SMEM_BYTES 174080               // 170 KB -> 1 CTA/SM

// named barriers: FULL[b] = 1+b (producer done filling b),
//                 EMPTY[b] = 3+b (consumers done reading b)
#define BAR_SYNC(id)   asm volatile("bar.sync %0, %1;"   :: "r"(id), "r"(NTHREADS) : "memory")
#define BAR_ARRIVE(id) asm volatile("bar.arrive %0, %1;" :: "r"(id), "r"(NTHREADS) : "memory")

__device__ __forceinline__ void ldsm_x4(uint32_t (&r)[4], uint32_t addr) {
    asm volatile("ldmatrix.sync.aligned.m8n8.x4.shared.b16 {%0,%1,%2,%3}, [%4];"
                 : "=r"(r[0]), "=r"(r[1]), "=r"(r[2]), "=r"(r[3]) : "r"(addr));
}
__device__ __forceinline__ void ldsm_x4_t(uint32_t (&r)[4], uint32_t addr) {
    asm volatile("ldmatrix.sync.aligned.m8n8.x4.trans.shared.b16 {%0,%1,%2,%3}, [%4];"
                 : "=r"(r[0]), "=r"(r[1]), "=r"(r[2]), "=r"(r[3]) : "r"(addr));
}
#define MMA(C, A, b0, b1) asm volatile( \
    "mma.sync.aligned.m16n8k16.row.col.f32.f16.f16.f32 " \
    "{%0,%1,%2,%3}, {%4,%5,%6,%7}, {%8,%9}, {%0,%1,%2,%3};" \
    : "+f"((C)[0]), "+f"((C)[1]), "+f"((C)[2]), "+f"((C)[3]) \
    : "r"((A)[0]), "r"((A)[1]), "r"((A)[2]), "r"((A)[3]), "r"(b0), "r"(b1))

__device__ __forceinline__ uint32_t hbits(__half2 v) {
    return *reinterpret_cast<uint32_t*>(&v);
}
__device__ __forceinline__ uint32_t packh2(float x, float y) {
    __half2 h = __floats2half2_rn(x, y);
    return hbits(h);
}
// split a float pair into (hi, lo) packed f16x2
__device__ __forceinline__ void split2h(float x, float y, uint32_t &hi, uint32_t &lo) {
    __half2 h = __floats2half2_rn(x, y);
    float2 g = __half22float2(h);
    __half2 l = __floats2half2_rn(x - g.x, y - g.y);
    hi = hbits(h); lo = hbits(l);
}

// producer helpers: batch of 8 (K,V) float4 pairs, idx = p + (base+j)*64
#define P_LOAD(KA, VA, base_i) \
    _Pragma("unroll") \
    for (int j = 0; j < 8; j++) { \
        int idx = p + ((base_i) + j) * 64; \
        size_t g = kvb + (size_t)(idx >> 5) * (NKV * D_) + ((idx & 31) << 2); \
        KA[j] = *(const float4*)(K + g); \
        VA[j] = *(const float4*)(V + g); \
    }
#define P_STORE(KA, VA, base_i) \
    _Pragma("unroll") \
    for (int j = 0; j < 8; j++) { \
        int idx = p + ((base_i) + j) * 64; \
        int off = bo + (idx >> 5) * ROWB + ((idx & 31) << 2) * 2; \
        uint32_t h0, l0, h1, l1; \
        split2h(KA[j].x, KA[j].y, h0, l0); \
        split2h(KA[j].z, KA[j].w, h1, l1); \
        *(uint2*)(smem + off + KHI_O) = make_uint2(h0, h1); \
        *(uint2*)(smem + off + KLO_O) = make_uint2(l0, l1); \
        h0 = packh2(VA[j].x, VA[j].y); \
        h1 = packh2(VA[j].z, VA[j].w); \
        *(uint2*)(smem + off + V_O) = make_uint2(h0, h1); \
    }

__global__ void __launch_bounds__(NTHREADS, 1)
swa_mma_kernel(const float* __restrict__ Q, const float* __restrict__ K,
               const float* __restrict__ V, float* __restrict__ Out)
{
    extern __shared__ char smem[];
    uint32_t sbase;
    asm("{ .reg .u64 t; cvta.to.shared.u64 t, %1; cvt.u32.u64 %0, t; }"
        : "=r"(sbase) : "l"(smem));

    const int tid  = threadIdx.x;
    const int lane = tid & 31;
    const int wid  = tid >> 5;
    const int m0   = blockIdx.x * BM;
    const int h    = blockIdx.y;
    const int bb   = blockIdx.z;
    const int kh   = h >> 1;

    const int kb0 = (m0 >= WIN) ? ((m0 - WIN) >> 6) : 0;
    const int kbm = (m0 >> 6) + 1;

    const size_t kvhead = (size_t)(bb * T_) * (NKV * D_) + (size_t)kh * D_;

    if (wid >= 8) {
        // ============ PRODUCER (warps 8-9): software-pipelined ============
        // two register sets of 8 (K,V) float4 pairs -> up to 32 LDG.128 in
        // flight before the first convert; 16 sustained.
        const int p = tid - NCONS;
        for (int t = kb0; t <= kbm; t++) {
            const int b = (t - kb0) & 1;
            if (t - kb0 >= 2) BAR_SYNC(3 + b);        // wait consumers freed b
            const size_t kvb = kvhead + (size_t)(t * BN) * (NKV * D_);
            const int bo = BUF_OFF + b * BUFSZ;
            float4 kA[8], vA[8], kB[8], vB[8];
            P_LOAD(kA, vA, 0);
            P_LOAD(kB, vB, 8);
            P_STORE(kA, vA, 0);
            P_LOAD(kA, vA, 16);
            P_STORE(kB, vB, 8);
            P_LOAD(kB, vB, 24);
            P_STORE(kA, vA, 16);
            P_STORE(kB, vB, 24);
            BAR_SYNC(1 + b);                          // publish FULL[b]
        }
        return;
    }

    // ================= CONSUMERS (warps 0-7, 256 threads) =================
    const int rb = wid * 16;            // warp owns rows [16w, 16w+16)
    const int tq = lane >> 2;           // 0..7
    const int tr = lane & 3;            // 0..3

    // ---- load + split Q tile (128 x 128) ----
    {
        const size_t qbase = ((size_t)(bb * T_ + m0) * NH + h) * D_;
        #pragma unroll
        for (int i = 0; i < 16; i++) {
            int idx = tid + i * NCONS;               // 4096 float4s
            int row = idx >> 5, c4 = (idx & 31) << 2;
            float4 f = *(const float4*)(Q + qbase + (size_t)row * (NH * D_) + c4);
            uint32_t h0, l0, h1, l1;
            split2h(f.x, f.y, h0, l0);
            split2h(f.z, f.w, h1, l1);
            int off = row * ROWB + c4 * 2;
            *(uint2*)(smem + QHI_OFF + off) = make_uint2(h0, h1);
            *(uint2*)(smem + QLO_OFF + off) = make_uint2(l0, l1);
        }
    }

    // ldmatrix base addresses (lane-dependent parts precomputed)
    const uint32_t a_q_hi = sbase + QHI_OFF + (rb + (lane & 15)) * ROWB + ((lane >> 4) << 3) * 2;
    const uint32_t a_q_lo = a_q_hi + (QLO_OFF - QHI_OFF);
    const int k_row = ((lane >> 4) << 3) + (lane & 7);
    const int k_col = (((lane >> 3) & 1) << 3);
    const uint32_t a_k_hi = sbase + BUF_OFF + KHI_O + k_row * ROWB + k_col * 2;
    const uint32_t a_k_lo = a_k_hi + (KLO_O - KHI_O);
    const int v_row = (((lane >> 3) & 1) << 3) + (lane & 7);
    const int v_col = ((lane >> 4) << 3);
    const uint32_t a_v = sbase + BUF_OFF + V_O + v_row * ROWB + v_col * 2;

    // O accumulators: 16 d-tiles x 4 f32  (c0,c1 row R0; c2,c3 row R1)
    float O[16][4];
    #pragma unroll
    for (int j = 0; j < 16; j++)
        #pragma unroll
        for (int e = 0; e < 4; e++) O[j][e] = 0.f;

    float mr0 = -1e29f, mr1 = -1e29f, lr0 = 0.f, lr1 = 0.f;

    for (int t = kb0; t <= kbm; t++) {
        const int n0 = t * BN;
        const int b  = (t - kb0) & 1;
        const uint32_t bofs = b * BUFSZ;
        const bool need_mask = (n0 >= m0) || (n0 + WIN < m0 + BM);

        BAR_SYNC(1 + b);   // wait FULL[b] (also drains our Q STS on 1st iter)

        // ---- S = Q K^T : 16 rows x 64 keys per warp, 3-MMA f16 split ----
        float S[8][4];
        #pragma unroll
        for (int j = 0; j < 8; j++)
            #pragma unroll
            for (int e = 0; e < 4; e++) S[j][e] = 0.f;

        #pragma unroll
        for (int ks = 0; ks < 8; ks++) {            // k = 16*ks over d=128
            uint32_t ah[4], al[4], bh[4][4], bl[4][4];
            ldsm_x4(ah, a_q_hi + ks * 32);
            ldsm_x4(al, a_q_lo + ks * 32);
            #pragma unroll
            for (int np = 0; np < 4; np++)
                ldsm_x4(bh[np], a_k_hi + bofs + np * 16 * ROWB + ks * 32);
            #pragma unroll
            for (int np = 0; np < 4; np++) {        // term 1: Qhi * Khi
                MMA(S[2*np],   ah, bh[np][0], bh[np][1]);
                MMA(S[2*np+1], ah, bh[np][2], bh[np][3]);
            }
            #pragma unroll
            for (int np = 0; np < 4; np++) {        // term 2: Qlo * Khi
                MMA(S[2*np],   al, bh[np][0], bh[np][1]);
                MMA(S[2*np+1], al, bh[np][2], bh[np][3]);
            }
            #pragma unroll
            for (int np = 0; np < 4; np++)
                ldsm_x4(bl[np], a_k_lo + bofs + np * 16 * ROWB + ks * 32);
            #pragma unroll
            for (int np = 0; np < 4; np++) {        // term 3: Qhi * Klo
                MMA(S[2*np],   ah, bl[np][0], bl[np][1]);
                MMA(S[2*np+1], ah, bl[np][2], bl[np][3]);
            }
        }

        if (need_mask) {
            const int q0 = m0 + rb + tq, q1 = q0 + 8;
            #pragma unroll
            for (int j = 0; j < 8; j++) {
                #pragma unroll
                for (int e = 0; e < 2; e++) {
                    int kp = n0 + 8 * j + 2 * tr + e;
                    if (kp > q0 || kp + WIN <= q0) S[j][e]     = -1e30f;
                    if (kp > q1 || kp + WIN <= q1) S[j][2 + e] = -1e30f;
                }
            }
        }

        // ---- online softmax (rows fully warp-private; quad reductions) ----
        float mx0 = -1e30f, mx1 = -1e30f;
        #pragma unroll
        for (int j = 0; j < 8; j++) {
            mx0 = fmaxf(mx0, fmaxf(S[j][0], S[j][1]));
            mx1 = fmaxf(mx1, fmaxf(S[j][2], S[j][3]));
        }
        mx0 = fmaxf(mx0, __shfl_xor_sync(0xffffffffu, mx0, 1));
        mx0 = fmaxf(mx0, __shfl_xor_sync(0xffffffffu, mx0, 2));
        mx1 = fmaxf(mx1, __shfl_xor_sync(0xffffffffu, mx1, 1));
        mx1 = fmaxf(mx1, __shfl_xor_sync(0xffffffffu, mx1, 2));
        const float mn0 = fmaxf(mr0, mx0), mn1 = fmaxf(mr1, mx1);
        const float sc0 = __expf(mr0 - mn0), sc1 = __expf(mr1 - mn1);
        mr0 = mn0; mr1 = mn1;

        float s0 = 0.f, s1 = 0.f;
        #pragma unroll
        for (int j = 0; j < 8; j++) {
            S[j][0] = __expf(S[j][0] - mn0); s0 += S[j][0];
            S[j][1] = __expf(S[j][1] - mn0); s0 += S[j][1];
            S[j][2] = __expf(S[j][2] - mn1); s1 += S[j][2];
            S[j][3] = __expf(S[j][3] - mn1); s1 += S[j][3];
        }
        s0 += __shfl_xor_sync(0xffffffffu, s0, 1);
        s0 += __shfl_xor_sync(0xffffffffu, s0, 2);
        s1 += __shfl_xor_sync(0xffffffffu, s1, 1);
        s1 += __shfl_xor_sync(0xffffffffu, s1, 2);
        lr0 = lr0 * sc0 + s0;
        lr1 = lr1 * sc1 + s1;

        #pragma unroll
        for (int j = 0; j < 16; j++) {
            O[j][0] *= sc0; O[j][1] *= sc0;
            O[j][2] *= sc1; O[j][3] *= sc1;
        }

        // ---- O += P V : P single-f16, V single-f16 ----
        #pragma unroll
        for (int j = 0; j < 4; j++) {               // key k-steps (16 keys)
            uint32_t ph[4];
            ph[0] = packh2(S[2*j][0],   S[2*j][1]);
            ph[1] = packh2(S[2*j][2],   S[2*j][3]);
            ph[2] = packh2(S[2*j+1][0], S[2*j+1][1]);
            ph[3] = packh2(S[2*j+1][2], S[2*j+1][3]);
            uint32_t bv[8][4];
            #pragma unroll
            for (int dp = 0; dp < 8; dp++)
                ldsm_x4_t(bv[dp], a_v + bofs + j * 16 * ROWB + dp * 32);
            #pragma unroll
            for (int dp = 0; dp < 8; dp++) {
                MMA(O[2*dp],   ph, bv[dp][0], bv[dp][1]);
                MMA(O[2*dp+1], ph, bv[dp][2], bv[dp][3]);
            }
        }

        if (t + 2 <= kbm) BAR_ARRIVE(3 + b);        // release EMPTY[b]
    }

    // ---- epilogue: normalize and store ----
    const float inv0 = 1.0f / lr0, inv1 = 1.0f / lr1;
    const int r0g = m0 + rb + tq;
    const size_t ob0 = ((size_t)(bb * T_ + r0g) * NH + h) * D_;
    const size_t ob1 = ((size_t)(bb * T_ + r0g + 8) * NH + h) * D_;
    #pragma unroll
    for (int j = 0; j < 16; j++) {
        int col = 8 * j + 2 * tr;
        *(float2*)(Out + ob0 + col) = make_float2(O[j][0] * inv0, O[j][1] * inv0);
        *(float2*)(Out + ob1 + col) = make_float2(O[j][2] * inv1, O[j][3] * inv1);
    }
}

extern "C" void kernel_launch(void* const* d_in, const int* in_sizes, int n_in,
                              void* d_out, int out_size) {
    (void)in_sizes; (void)n_in; (void)out_size;
    const float* Q = (const float*)d_in[0];
    const float* K = (const float*)d_in[1];
    const float* V = (const float*)d_in[2];
    float* O = (float*)d_out;

    cudaFuncSetAttribute(swa_mma_kernel,
                         cudaFuncAttributeMaxDynamicSharedMemorySize, SMEM_BYTES);

    dim3 grid(T_ / BM, NH, B_);   // 32 x 16 x 4 = 2048 CTAs
    swa_mma_kernel<<<grid, NTHREADS, SMEM_BYTES>>>(Q, K, V, O);
}